// round 5
// baseline (speedup 1.0000x reference)
#include <cuda_runtime.h>
#include <cuda_fp16.h>

#define HH 800
#define WW 800
#define PP 8
#define NPTS 200000
#define DIM 8
#define HID 256
#define NPIX (HH*WW)
#define NSLOT (NPIX*PP)
#define Z_THRESH 0.2f

typedef unsigned long long ull;

// -------- persistent scratch (no allocs allowed) --------
__device__ float4 g_acc4[NPTS];        // sum dir.x, dir.y, dir.z, cos
__device__ unsigned g_cnt[NPTS];       // count | (valid_count << 16)
__device__ unsigned g_minidx[NPTS];    // min flat slot index
__device__ uint4 g_feat[NPTS];         // MLP output per point, 8 x fp16

// -------- f32x2 packed helpers --------
__device__ __forceinline__ ull fma2(ull a, ull b, ull c) {
    ull d;
    asm("fma.rn.f32x2 %0, %1, %2, %3;" : "=l"(d) : "l"(a), "l"(b), "l"(c));
    return d;
}
__device__ __forceinline__ ull pack2(float lo, float hi) {
    ull r;
    asm("mov.b64 %0, {%1, %2};" : "=l"(r) : "f"(lo), "f"(hi));
    return r;
}
__device__ __forceinline__ void unpack2(ull v, float& lo, float& hi) {
    asm("mov.b64 {%0, %1}, %2;" : "=f"(lo), "=f"(hi) : "l"(v));
}

// -------- kernel 1: reset accumulators --------
__global__ void k_init() {
    int i = blockIdx.x * blockDim.x + threadIdx.x;
    if (i < NPTS) {
        g_acc4[i] = make_float4(0.f, 0.f, 0.f, 0.f);
        g_cnt[i] = 0u;
        g_minidx[i] = 0xFFFFFFFFu;
    }
}

// -------- kernel 2: segment scatter (3 atomics, 6 L2 words per slot) --------
__global__ void __launch_bounds__(256) k_scatter(
    const float* __restrict__ zbufs,
    const float* __restrict__ ray,
    const int* __restrict__ idbufs)
{
    int pix = blockIdx.x * blockDim.x + threadIdx.x;
    if (pix >= NPIX) return;

    const float4* zb4 = (const float4*)zbufs;
    const int4*   id4 = (const int4*)idbufs;
    float4 za = zb4[pix * 2 + 0];
    float4 zb = zb4[pix * 2 + 1];
    int4   ia = id4[pix * 2 + 0];
    int4   ib = id4[pix * 2 + 1];

    float dx = __ldg(ray + pix * 7 + 3);
    float dy = __ldg(ray + pix * 7 + 4);
    float dz = __ldg(ray + pix * 7 + 5);
    float cs = __ldg(ray + pix * 7 + 6);
    float4 v4 = make_float4(dx, dy, dz, cs);

    int   ids[8] = {ia.x, ia.y, ia.z, ia.w, ib.x, ib.y, ib.z, ib.w};
    float zs[8]  = {za.x, za.y, za.z, za.w, zb.x, zb.y, zb.z, zb.w};

    unsigned ibase = (unsigned)pix * PP;
#pragma unroll
    for (int p = 0; p < 8; p++) {
        int id = ids[p];
        atomicAdd(&g_acc4[id], v4);
        atomicAdd(&g_cnt[id], 1u + (zs[p] > Z_THRESH ? 0x10000u : 0u));
        atomicMin(&g_minidx[id], ibase + p);
    }
}

// -------- kernel 3: per-point MLP, f32x2 over j-pairs, 2 pts/thread -------
__global__ void __launch_bounds__(128) k_mlp(
    const float* __restrict__ zbufs,
    const float* __restrict__ ray,
    const float* __restrict__ W1,
    const float* __restrict__ b1,
    const float* __restrict__ W2,
    const float* __restrict__ b2)
{
    // per j-pair (jp = j/2):
    //  sw1p[jp][k] = (W1[k][2jp], W1[k][2jp+1]) for k=0..5 ; [6]=(b1 pair); [7]=pad
    //  sw2p[jp][d] = (W2[2jp][d], W2[2jp+1][d]) for d=0..7
    __shared__ ull sw1p[128 * 8];
    __shared__ ull sw2p[128 * 8];

    int tid = threadIdx.x;
    {
        int jp = tid;                 // 128 threads <-> 128 j-pairs
        int j0 = 2 * jp;
#pragma unroll
        for (int k = 0; k < 6; k++)
            sw1p[jp * 8 + k] = pack2(W1[k * HID + j0], W1[k * HID + j0 + 1]);
        sw1p[jp * 8 + 6] = pack2(b1[j0], b1[j0 + 1]);
        sw1p[jp * 8 + 7] = 0ULL;
#pragma unroll
        for (int d = 0; d < 8; d++)
            sw2p[jp * 8 + d] = pack2(W2[j0 * 8 + d], W2[(j0 + 1) * 8 + d]);
    }
    __syncthreads();

    float o0 = __ldg(ray + 0), o1 = __ldg(ray + 1), o2 = __ldg(ray + 2);

    int base = blockIdx.x * 256 + tid;   // 2 points, strided by 128
    ull  x2[2][6];
    ull  f2[2][8];
    bool ok[2];

#pragma unroll
    for (int k = 0; k < 2; k++) {
        int pt = base + k * 128;
        bool inb = pt < NPTS;
        int ptc = inb ? pt : 0;

        float4 a4 = g_acc4[ptc];
        unsigned cw = g_cnt[ptc];
        unsigned cnt = cw & 0xFFFFu;
        unsigned vld = cw >> 16;
        unsigned mi = g_minidx[ptc];
        mi = mi < (NSLOT - 1) ? mi : (NSLOT - 1);
        float zf = __ldg(zbufs + mi);

        ok[k] = inb && (cnt > 0u) && (vld > 0u);
        float safe = fmaxf((float)cnt, 1.0f);
        float inv = 1.0f / safe;
        float dux = a4.x * inv, duy = a4.y * inv, duz = a4.z * inv;
        float cosm = a4.w * inv;
        float zc = ok[k] ? (zf / cosm) : 0.0f;

        float xv[6];
        xv[0] = ok[k] ? o0 + zc * dux : 0.f;
        xv[1] = ok[k] ? o1 + zc * duy : 0.f;
        xv[2] = ok[k] ? o2 + zc * duz : 0.f;
        xv[3] = ok[k] ? dux : 0.f;
        xv[4] = ok[k] ? duy : 0.f;
        xv[5] = ok[k] ? duz : 0.f;
#pragma unroll
        for (int i = 0; i < 6; i++) x2[k][i] = pack2(xv[i], xv[i]);
#pragma unroll
        for (int d = 0; d < 8; d++) f2[k][d] = pack2(__ldg(b2 + d), 0.f);
    }

#pragma unroll 2
    for (int jp = 0; jp < 128; jp++) {
        const ull* w1 = &sw1p[jp * 8];
        const ull* w2 = &sw2p[jp * 8];
        ull bp = w1[6];
        ull wk0 = w1[0], wk1 = w1[1], wk2 = w1[2];
        ull wk3 = w1[3], wk4 = w1[4], wk5 = w1[5];

        ull h[2];
#pragma unroll
        for (int k = 0; k < 2; k++) {
            ull t = bp;
            t = fma2(x2[k][0], wk0, t);
            t = fma2(x2[k][1], wk1, t);
            t = fma2(x2[k][2], wk2, t);
            t = fma2(x2[k][3], wk3, t);
            t = fma2(x2[k][4], wk4, t);
            t = fma2(x2[k][5], wk5, t);
            float lo, hi;
            unpack2(t, lo, hi);
            lo = fmaxf(lo, 0.0f);
            hi = fmaxf(hi, 0.0f);
            h[k] = pack2(lo, hi);
        }
#pragma unroll
        for (int d = 0; d < 8; d++) {
            ull wd = w2[d];
            f2[0][d] = fma2(h[0], wd, f2[0][d]);
            f2[1][d] = fma2(h[1], wd, f2[1][d]);
        }
    }

#pragma unroll
    for (int k = 0; k < 2; k++) {
        int pt = base + k * 128;
        if (pt >= NPTS) continue;
        float f[8];
        if (ok[k]) {
#pragma unroll
            for (int d = 0; d < 8; d++) {
                float lo, hi;
                unpack2(f2[k][d], lo, hi);
                f[d] = lo + hi;
            }
        } else {
#pragma unroll
            for (int d = 0; d < 8; d++) f[d] = 0.f;
        }
        __half2 p0 = __floats2half2_rn(f[0], f[1]);
        __half2 p1 = __floats2half2_rn(f[2], f[3]);
        __half2 p2 = __floats2half2_rn(f[4], f[5]);
        __half2 p3 = __floats2half2_rn(f[6], f[7]);
        uint4 v;
        v.x = *(unsigned*)&p0;
        v.y = *(unsigned*)&p1;
        v.z = *(unsigned*)&p2;
        v.w = *(unsigned*)&p3;
        g_feat[pt] = v;
    }
}

// -------- kernel 4: gather (1 LDG.128 per slot), coalesced plane writes ----
// block = 256 = 8 warps; warp w owns p=w for 32 consecutive pixels.
__global__ void __launch_bounds__(256) k_out(
    const int* __restrict__ idbufs,
    float* __restrict__ out)
{
    int t = threadIdx.x;
    int p = t >> 5;                   // 0..7
    int lane = t & 31;
    int pix = blockIdx.y * WW + blockIdx.x * 32 + lane;

    int id = __ldg(idbufs + pix * PP + p);

    uint4 g = __ldg(&g_feat[id]);     // all 8 channels, fp16, one wavefront
    float2 f0 = __half22float2(*(__half2*)&g.x);
    float2 f1 = __half22float2(*(__half2*)&g.y);
    float2 f2v = __half22float2(*(__half2*)&g.z);
    float2 f3 = __half22float2(*(__half2*)&g.w);

    float* o = out + (size_t)(p * 8) * NPIX + pix;
    o[0 * NPIX] = f0.x;
    o[1 * NPIX] = f0.y;
    o[2 * NPIX] = f1.x;
    o[3 * NPIX] = f1.y;
    o[4 * NPIX] = f2v.x;
    o[5 * NPIX] = f2v.y;
    o[6 * NPIX] = f3.x;
    o[7 * NPIX] = f3.y;
}

extern "C" void kernel_launch(void* const* d_in, const int* in_sizes, int n_in,
                              void* d_out, int out_size)
{
    const float* zbufs = (const float*)d_in[0];
    const float* ray   = (const float*)d_in[1];
    const float* W1    = (const float*)d_in[2];
    const float* b1    = (const float*)d_in[3];
    const float* W2    = (const float*)d_in[4];
    const float* b2    = (const float*)d_in[5];
    const int*   idb   = (const int*)d_in[6];
    float* out = (float*)d_out;

    k_init<<<(NPTS + 255) / 256, 256>>>();
    k_scatter<<<(NPIX + 255) / 256, 256>>>(zbufs, ray, idb);
    k_mlp<<<(NPTS + 255) / 256, 128>>>(zbufs, ray, W1, b1, W2, b2);
    k_out<<<dim3(WW / 32, HH), 256>>>(idb, out);
}